// round 12
// baseline (speedup 1.0000x reference)
#include <cuda_runtime.h>
#include <cuda_bf16.h>
#include <math.h>

// Problem constants (fixed-shape problem)
#define BB 128
#define SS 512
#define EE 768
#define CC 9

#define L2E 1.4426950408889634f
#define LN2 0.6931471805599453f
#define FULLM 0xffffffffu

__device__ float g_scratch[BB];

// ---- fast MUFU math (single SASS op each) ---------------------------------
__device__ __forceinline__ float fast_ex2(float x) {
    float r;
    asm("ex2.approx.f32 %0, %1;" : "=f"(r) : "f"(x));
    return r;
}
__device__ __forceinline__ float fast_lg2(float x) {
    float r;
    asm("lg2.approx.f32 %0, %1;" : "=f"(r) : "f"(x));
    return r;
}

// ---- packed f32x2 helpers (sm_103a FFMA2 path) ----------------------------
__device__ __forceinline__ unsigned long long pk2(float a, float b) {
    unsigned long long r;
    asm("mov.b64 %0, {%1, %2};" : "=l"(r) : "f"(a), "f"(b));
    return r;
}
__device__ __forceinline__ unsigned long long fma2(
    unsigned long long a, unsigned long long b, unsigned long long c) {
    unsigned long long d;
    asm("fma.rn.f32x2 %0, %1, %2, %3;" : "=l"(d) : "l"(a), "l"(b), "l"(c));
    return d;
}
__device__ __forceinline__ float upsum(unsigned long long p) {
    float lo, hi;
    asm("mov.b64 {%0, %1}, %2;" : "=f"(lo), "=f"(hi) : "l"(p));
    return lo + hi;
}

// ---------------------------------------------------------------------------
// Kernel 1: emissions = enc @ W^T + b
// warp = 4 row-groups x 8 k-sublanes; 2 rows/thread, packed f32x2 FMAs.
// Block 256 threads -> 64 rows; grid 1024.
// ---------------------------------------------------------------------------
__global__ __launch_bounds__(256) void k_emissions(
    const float* __restrict__ enc, const float* __restrict__ W,
    const float* __restrict__ bias, float* __restrict__ em)
{
    __shared__ float4 sW[CC * 192];   // 9 x 768 floats as float4
    __shared__ float  sB[CC];

    int tid = threadIdx.x;
    const float4* Wv = reinterpret_cast<const float4*>(W);
    for (int i = tid; i < CC * 192; i += 256) sW[i] = Wv[i];
    if (tid < CC) sB[tid] = bias[tid];
    __syncthreads();

    int warp = tid >> 5, lane = tid & 31;
    int r = lane >> 3, sub = lane & 7;
    int rowbase = blockIdx.x * 64 + warp * 8 + r;   // rows: rowbase, rowbase+4

    const float4* e0 = reinterpret_cast<const float4*>(enc) + (size_t)rowbase * 192;

    unsigned long long acc[2][CC];
#pragma unroll
    for (int j = 0; j < 2; j++)
#pragma unroll
        for (int c = 0; c < CC; c++) acc[j][c] = pk2(0.f, 0.f);

#pragma unroll 2
    for (int i = 0; i < 12; i++) {
        int ka = i * 16 + sub;        // float4 idx, chunk A
        int kb = ka + 8;              // chunk B
        float4 ea0 = __ldg(&e0[ka]);
        float4 ea1 = __ldg(&e0[kb]);
        float4 eb0 = __ldg(&e0[768 + ka]);   // row +4
        float4 eb1 = __ldg(&e0[768 + kb]);
        unsigned long long a0l = pk2(ea0.x, ea0.y), a0h = pk2(ea0.z, ea0.w);
        unsigned long long a1l = pk2(ea1.x, ea1.y), a1h = pk2(ea1.z, ea1.w);
        unsigned long long b0l = pk2(eb0.x, eb0.y), b0h = pk2(eb0.z, eb0.w);
        unsigned long long b1l = pk2(eb1.x, eb1.y), b1h = pk2(eb1.z, eb1.w);
#pragma unroll
        for (int c = 0; c < CC; c++) {
            float4 wa = sW[c * 192 + ka];
            float4 wb = sW[c * 192 + kb];
            unsigned long long wal = pk2(wa.x, wa.y), wah = pk2(wa.z, wa.w);
            unsigned long long wbl = pk2(wb.x, wb.y), wbh = pk2(wb.z, wb.w);
            acc[0][c] = fma2(a0l, wal, acc[0][c]);
            acc[0][c] = fma2(a0h, wah, acc[0][c]);
            acc[0][c] = fma2(a1l, wbl, acc[0][c]);
            acc[0][c] = fma2(a1h, wbh, acc[0][c]);
            acc[1][c] = fma2(b0l, wal, acc[1][c]);
            acc[1][c] = fma2(b0h, wah, acc[1][c]);
            acc[1][c] = fma2(b1l, wbl, acc[1][c]);
            acc[1][c] = fma2(b1h, wbh, acc[1][c]);
        }
    }

#pragma unroll
    for (int j = 0; j < 2; j++) {
        float s[CC];
#pragma unroll
        for (int c = 0; c < CC; c++) {
            float v = upsum(acc[j][c]);
            v += __shfl_xor_sync(FULLM, v, 4);
            v += __shfl_xor_sync(FULLM, v, 2);
            v += __shfl_xor_sync(FULLM, v, 1);
            s[c] = v;
        }
        float myv = s[0];
#pragma unroll
        for (int c = 1; c < 8; c++) if (sub == c) myv = s[c];
        size_t obase = (size_t)(rowbase + 4 * j) * CC;
        em[obase + sub] = myv + sB[sub];
        if (sub == 0) em[obase + 8] = s[8] + sB[8];
    }
}

// ---------------------------------------------------------------------------
// Kernel 2: CRF. Block = 64 threads, ONE batch per block (grid 128).
//   warp0: dual-direction recursion (lanes 0-8 fwd alpha, 16-24 bwd gamma),
//          single-MUFU ex2/lg2 on the critical path.
//   warp1: numerator (parallel gathers).
// tags/mask dtypes probed at runtime (int64 vs int32 tags; u8 vs i32 mask).
// ---------------------------------------------------------------------------
__global__ __launch_bounds__(64) void k_crf(
    const float* __restrict__ em_g,
    const float* __restrict__ startt, const float* __restrict__ endt,
    const float* __restrict__ trans,
    const void* __restrict__ tags_raw, const void* __restrict__ mask_raw)
{
    __shared__ float sem[SS * CC];           // 18KB
    __shared__ unsigned char smk[SS];
    __shared__ float snum, sden;
    __shared__ float sh[12];

    int tid = threadIdx.x;
    int lane = tid & 31;
    int w = tid >> 5;
    int b = blockIdx.x;

    // ---------- dtype probes ----------
    const long long* tg64 = (const long long*)tags_raw;
    const int*       tg32 = (const int*)tags_raw;
    long long tprobe = tg64[lane];
    unsigned badt = __ballot_sync(FULLM, (tprobe < 0) || (tprobe >= CC));
    bool tags64 = (badt == 0u);

    const unsigned int* m32 = (const unsigned int*)mask_raw;
    const unsigned char* m8 = (const unsigned char*)mask_raw;
    unsigned int mprobe = m32[lane];
    unsigned badm = __ballot_sync(FULLM, mprobe > 1u);
    bool mask8 = (badm != 0u);

    // ---------- stage emissions + mask (all 64 threads) ----------
    {
        const float4* src = reinterpret_cast<const float4*>(em_g + (size_t)b * SS * CC);
        float4* dst = reinterpret_cast<float4*>(sem);
        for (int i = tid; i < (SS * CC) / 4; i += 64) dst[i] = __ldg(&src[i]);
        if (mask8) {
            const unsigned int* ms = reinterpret_cast<const unsigned int*>(m8 + (size_t)b * SS);
            unsigned int* md = reinterpret_cast<unsigned int*>(smk);
            for (int i = tid; i < SS / 4; i += 64) md[i] = __ldg(&ms[i]);
        } else {
            const unsigned int* ms = m32 + (size_t)b * SS;
            for (int s = tid; s < SS; s += 64)
                smk[s] = (unsigned char)(__ldg(&ms[s]) != 0u);
        }
    }
    __syncthreads();

    if (w == 1) {
        // ---------------- numerator ----------------
        const long long* tb64 = tg64 + (size_t)b * SS;
        const int*       tb32 = tg32 + (size_t)b * SS;
        float pnum = 0.f;
        int plen = 0;
#pragma unroll 4
        for (int it = 0; it < SS / 32; it++) {
            int s = it * 32 + lane;
            int t = tags64 ? (int)__ldg(&tb64[s]) : __ldg(&tb32[s]);
            int mv = smk[s];
            plen += mv;
            if (s >= 1 && mv) {
                int tp = tags64 ? (int)__ldg(&tb64[s - 1]) : __ldg(&tb32[s - 1]);
                pnum += __ldg(&trans[tp * CC + t]) + sem[s * CC + t];
            }
        }
#pragma unroll
        for (int off = 16; off >= 1; off >>= 1) {
            pnum += __shfl_xor_sync(FULLM, pnum, off);
            plen += __shfl_xor_sync(FULLM, plen, off);
        }
        int t0 = tags64 ? (int)__ldg(&tb64[0]) : __ldg(&tb32[0]);
        int tl = tags64 ? (int)__ldg(&tb64[plen - 1]) : __ldg(&tb32[plen - 1]);
        if (lane == 0)
            snum = pnum + __ldg(&startt[t0]) + sem[t0] + __ldg(&endt[tl]);
    } else {
        // ---------------- dual-direction recursion ----------------
        bool isf = lane < 16;
        int g = isf ? lane : (lane - 16);
        bool active = (g < CC);
        int gc = active ? g : 0;

        float tk[CC];
#pragma unroll
        for (int k = 0; k < CC; k++) {
            int idx = isf ? (k * CC + gc) : (gc * CC + k);
            float tv = __expf(__ldg(&trans[idx]));
            tk[k] = active ? tv : 0.f;
        }

        float v;
        if (isf) v = active ? (__ldg(&startt[gc]) + sem[gc]) : 0.f;
        else     v = active ? (__ldg(&endt[gc]) + sem[(SS - 1) * CC + gc]) : 0.f;

        int ei  = isf ? (CC + gc) : ((SS - 2) * CC + gc);
        int dei = isf ? CC : -CC;
        int mi  = isf ? 1 : (SS - 1);
        int dmi = isf ? 1 : -1;
        int sbase = isf ? 0 : 16;

        float M = __shfl_sync(FULLM, v, sbase);
        float Ml2 = M * L2E;
        float em_prev = isf ? 0.f : sem[(SS - 1) * CC + gc];

        const int NIT = SS / 2 - 1;   // 255 combined iterations
        for (int i = 0; i < NIT; i++) {
            if ((i & 7) == 0) {
                M = __shfl_sync(FULLM, v, sbase);
                Ml2 = M * L2E;
            }
            float e = fast_ex2(fmaf(v, L2E, -Ml2));
            float e0 = __shfl_sync(FULLM, e, sbase + 0);
            float e1 = __shfl_sync(FULLM, e, sbase + 1);
            float e2 = __shfl_sync(FULLM, e, sbase + 2);
            float e3 = __shfl_sync(FULLM, e, sbase + 3);
            float e4 = __shfl_sync(FULLM, e, sbase + 4);
            float e5 = __shfl_sync(FULLM, e, sbase + 5);
            float e6 = __shfl_sync(FULLM, e, sbase + 6);
            float e7 = __shfl_sync(FULLM, e, sbase + 7);
            float e8 = __shfl_sync(FULLM, e, sbase + 8);
            float d0 = fmaf(tk[1], e1, tk[0] * e0); d0 = fmaf(tk[2], e2, d0);
            float d1 = fmaf(tk[4], e4, tk[3] * e3); d1 = fmaf(tk[5], e5, d1);
            float d2 = fmaf(tk[7], e7, tk[6] * e6); d2 = fmaf(tk[8], e8, d2);
            float dot = d0 + d1 + d2;
            float core = fmaf(fast_lg2(dot), LN2, M);
            float emt = sem[ei];
            int u = smk[mi];
            float cand = emt + core;
            float keep = isf ? v : (emt + v - em_prev);
            v = u ? cand : keep;
            em_prev = emt;
            ei += dei; mi += dmi;
        }

        // tail forward-only step t = S/2 (bwd lanes keep gamma_{S/2})
        {
            M = __shfl_sync(FULLM, v, sbase);
            Ml2 = M * L2E;
            float e = fast_ex2(fmaf(v, L2E, -Ml2));
            float e0 = __shfl_sync(FULLM, e, sbase + 0);
            float e1 = __shfl_sync(FULLM, e, sbase + 1);
            float e2 = __shfl_sync(FULLM, e, sbase + 2);
            float e3 = __shfl_sync(FULLM, e, sbase + 3);
            float e4 = __shfl_sync(FULLM, e, sbase + 4);
            float e5 = __shfl_sync(FULLM, e, sbase + 5);
            float e6 = __shfl_sync(FULLM, e, sbase + 6);
            float e7 = __shfl_sync(FULLM, e, sbase + 7);
            float e8 = __shfl_sync(FULLM, e, sbase + 8);
            float d0 = fmaf(tk[1], e1, tk[0] * e0); d0 = fmaf(tk[2], e2, d0);
            float d1 = fmaf(tk[4], e4, tk[3] * e3); d1 = fmaf(tk[5], e5, d1);
            float d2 = fmaf(tk[7], e7, tk[6] * e6); d2 = fmaf(tk[8], e8, d2);
            float dot = d0 + d1 + d2;
            float core = fmaf(fast_lg2(dot), LN2, M);
            float cand = sem[(SS / 2) * CC + gc] + core;
            if (lane < CC && smk[SS / 2]) v = cand;
        }

        // combine: den = LSE_c( alpha[c] + gamma[c] - em[S/2][c] )
        int src = (lane < CC) ? (lane + 16) : lane;
        float vb = __shfl_sync(FULLM, v, src);
        if (lane < CC) sh[lane] = v + vb - sem[(SS / 2) * CC + lane];
        __syncwarp();
        if (lane == 0) {
            float m = sh[0];
#pragma unroll
            for (int c = 1; c < CC; c++) m = fmaxf(m, sh[c]);
            float s = 0.f;
#pragma unroll
            for (int c = 0; c < CC; c++) s += __expf(sh[c] - m);
            sden = m + __logf(s);
        }
    }
    __syncthreads();

    if (tid == 0) g_scratch[b] = sden - snum;
}

// ---------------------------------------------------------------------------
// Kernel 3: deterministic mean over batch
// ---------------------------------------------------------------------------
__global__ __launch_bounds__(32) void k_final(float* __restrict__ out)
{
    int lane = threadIdx.x;
    float s = 0.f;
    for (int i = lane; i < BB; i += 32) s += g_scratch[i];
#pragma unroll
    for (int off = 16; off >= 1; off >>= 1)
        s += __shfl_xor_sync(FULLM, s, off);
    if (lane == 0) out[0] = s / (float)BB;
}

// emissions scratch (B*S*C floats = 2.25 MB)
__device__ float g_em[BB * SS * CC];

extern "C" void kernel_launch(void* const* d_in, const int* in_sizes, int n_in,
                              void* d_out, int out_size)
{
    const float* enc   = (const float*)d_in[0];
    const float* W     = (const float*)d_in[1];
    const float* bias  = (const float*)d_in[2];
    const float* stt   = (const float*)d_in[3];
    const float* ent   = (const float*)d_in[4];
    const float* trans = (const float*)d_in[5];
    const void*  tags  = d_in[6];
    const void*  mask  = d_in[7];
    float* out = (float*)d_out;

    float* em;
    cudaGetSymbolAddress((void**)&em, g_em);

    k_emissions<<<(BB * SS) / 64, 256>>>(enc, W, bias, em);
    k_crf<<<BB, 64>>>(em, stt, ent, trans, tags, mask);
    k_final<<<1, 32>>>(out);
}

// round 13
// speedup vs baseline: 1.0630x; 1.0630x over previous
#include <cuda_runtime.h>
#include <cuda_bf16.h>
#include <math.h>

#define BB 128
#define SS 512
#define EE 768
#define CC 9

#define L2E 1.4426950408889634f
#define LN2 0.6931471805599453f
#define FULLM 0xffffffffu

__device__ float g_scratch[BB];

// ---- fast MUFU math (single SASS op each) ---------------------------------
__device__ __forceinline__ float fast_ex2(float x) {
    float r; asm("ex2.approx.f32 %0, %1;" : "=f"(r) : "f"(x)); return r;
}
__device__ __forceinline__ float fast_lg2(float x) {
    float r; asm("lg2.approx.f32 %0, %1;" : "=f"(r) : "f"(x)); return r;
}

// ---------------------------------------------------------------------------
// Kernel 1: emissions = enc @ W^T + b   (R5 scalar 4-row layout, occ-capped)
// warp = 4 row-groups x 8 k-sublanes; each thread accumulates 4 rows.
// ---------------------------------------------------------------------------
__global__ __launch_bounds__(256, 3) void k_emissions(
    const float* __restrict__ enc, const float* __restrict__ W,
    const float* __restrict__ bias, float* __restrict__ em)
{
    __shared__ float4 sW[CC * 192];
    __shared__ float  sB[CC];

    int tid = threadIdx.x;
    const float4* Wv = reinterpret_cast<const float4*>(W);
    for (int i = tid; i < CC * 192; i += 256) sW[i] = Wv[i];
    if (tid < CC) sB[tid] = bias[tid];
    __syncthreads();

    int warp = tid >> 5, lane = tid & 31;
    int r = lane >> 3, sub = lane & 7;
    int rowbase = blockIdx.x * 128 + warp * 16 + r;  // rows rowbase + 4*j

    const float4* e0 = reinterpret_cast<const float4*>(enc) + (size_t)rowbase * 192;

    float acc[4][CC];
#pragma unroll
    for (int j = 0; j < 4; j++)
#pragma unroll
        for (int c = 0; c < CC; c++) acc[j][c] = 0.f;

#pragma unroll 4
    for (int i = 0; i < 24; i++) {
        int k4 = i * 8 + sub;
        float4 ea = __ldg(&e0[k4]);
        float4 eb = __ldg(&e0[768 + k4]);
        float4 ec = __ldg(&e0[1536 + k4]);
        float4 ed = __ldg(&e0[2304 + k4]);
#pragma unroll
        for (int c = 0; c < CC; c++) {
            float4 w = sW[c * 192 + k4];
            acc[0][c] = fmaf(ea.x, w.x, acc[0][c]);
            acc[0][c] = fmaf(ea.y, w.y, acc[0][c]);
            acc[0][c] = fmaf(ea.z, w.z, acc[0][c]);
            acc[0][c] = fmaf(ea.w, w.w, acc[0][c]);
            acc[1][c] = fmaf(eb.x, w.x, acc[1][c]);
            acc[1][c] = fmaf(eb.y, w.y, acc[1][c]);
            acc[1][c] = fmaf(eb.z, w.z, acc[1][c]);
            acc[1][c] = fmaf(eb.w, w.w, acc[1][c]);
            acc[2][c] = fmaf(ec.x, w.x, acc[2][c]);
            acc[2][c] = fmaf(ec.y, w.y, acc[2][c]);
            acc[2][c] = fmaf(ec.z, w.z, acc[2][c]);
            acc[2][c] = fmaf(ec.w, w.w, acc[2][c]);
            acc[3][c] = fmaf(ed.x, w.x, acc[3][c]);
            acc[3][c] = fmaf(ed.y, w.y, acc[3][c]);
            acc[3][c] = fmaf(ed.z, w.z, acc[3][c]);
            acc[3][c] = fmaf(ed.w, w.w, acc[3][c]);
        }
    }

#pragma unroll
    for (int j = 0; j < 4; j++)
#pragma unroll
        for (int c = 0; c < CC; c++) {
            acc[j][c] += __shfl_xor_sync(FULLM, acc[j][c], 4);
            acc[j][c] += __shfl_xor_sync(FULLM, acc[j][c], 2);
            acc[j][c] += __shfl_xor_sync(FULLM, acc[j][c], 1);
        }

#pragma unroll
    for (int j = 0; j < 4; j++) {
        float myv = acc[j][0];
#pragma unroll
        for (int c = 1; c < 8; c++) if (sub == c) myv = acc[j][c];
        size_t obase = (size_t)(rowbase + 4 * j) * CC;
        em[obase + sub] = myv + sB[sub];
        if (sub == 0) em[obase + 8] = acc[j][8] + sB[8];
    }
}

// ---------------------------------------------------------------------------
// Kernel 2: CRF. Block = 64 threads handles TWO batches.
//   warp0: dual-direction recursions for BOTH batches interleaved (ILP hides
//          MUFU/SHFL latency). lanes 0-8 fwd alpha, lanes 16-24 bwd gamma.
//   warp1: numerators for both batches.
// tags/mask dtypes probed at runtime.
// ---------------------------------------------------------------------------
__global__ __launch_bounds__(64) void k_crf(
    const float* __restrict__ em_g,
    const float* __restrict__ startt, const float* __restrict__ endt,
    const float* __restrict__ trans,
    const void* __restrict__ tags_raw, const void* __restrict__ mask_raw)
{
    __shared__ float sem0[SS * CC];
    __shared__ float sem1[SS * CC];
    __shared__ unsigned char smk0[SS];
    __shared__ unsigned char smk1[SS];
    __shared__ float snum[2];
    __shared__ float sden[2];
    __shared__ float shl[2][12];

    int tid = threadIdx.x;
    int lane = tid & 31;
    int w = tid >> 5;
    int b0 = blockIdx.x * 2;

    // ---------- dtype probes ----------
    const long long* tg64 = (const long long*)tags_raw;
    const int*       tg32 = (const int*)tags_raw;
    long long tprobe = tg64[lane];
    unsigned badt = __ballot_sync(FULLM, (tprobe < 0) || (tprobe >= CC));
    bool tags64 = (badt == 0u);

    const unsigned int* m32 = (const unsigned int*)mask_raw;
    const unsigned char* m8 = (const unsigned char*)mask_raw;
    unsigned int mprobe = m32[lane];
    unsigned badm = __ballot_sync(FULLM, mprobe > 1u);
    bool mask8 = (badm != 0u);

    // ---------- stage emissions + masks ----------
    {
        const float4* s0 = reinterpret_cast<const float4*>(em_g + (size_t)b0 * SS * CC);
        const float4* s1 = reinterpret_cast<const float4*>(em_g + (size_t)(b0 + 1) * SS * CC);
        float4* d0 = reinterpret_cast<float4*>(sem0);
        float4* d1 = reinterpret_cast<float4*>(sem1);
        for (int i = tid; i < (SS * CC) / 4; i += 64) {
            d0[i] = __ldg(&s0[i]);
            d1[i] = __ldg(&s1[i]);
        }
        if (mask8) {
            const unsigned int* ms0 = reinterpret_cast<const unsigned int*>(m8 + (size_t)b0 * SS);
            const unsigned int* ms1 = reinterpret_cast<const unsigned int*>(m8 + (size_t)(b0 + 1) * SS);
            unsigned int* md0 = reinterpret_cast<unsigned int*>(smk0);
            unsigned int* md1 = reinterpret_cast<unsigned int*>(smk1);
            for (int i = tid; i < SS / 4; i += 64) { md0[i] = __ldg(&ms0[i]); md1[i] = __ldg(&ms1[i]); }
        } else {
            const unsigned int* ms0 = m32 + (size_t)b0 * SS;
            const unsigned int* ms1 = m32 + (size_t)(b0 + 1) * SS;
            for (int s = tid; s < SS; s += 64) {
                smk0[s] = (unsigned char)(__ldg(&ms0[s]) != 0u);
                smk1[s] = (unsigned char)(__ldg(&ms1[s]) != 0u);
            }
        }
    }
    __syncthreads();

    if (w == 1) {
        // ---------------- numerators ----------------
#pragma unroll
        for (int p = 0; p < 2; p++) {
            const long long* tb64 = tg64 + (size_t)(b0 + p) * SS;
            const int*       tb32 = tg32 + (size_t)(b0 + p) * SS;
            const float* semp = p ? sem1 : sem0;
            const unsigned char* smkp = p ? smk1 : smk0;
            float pnum = 0.f;
            int plen = 0;
#pragma unroll 4
            for (int it = 0; it < SS / 32; it++) {
                int s = it * 32 + lane;
                int t = tags64 ? (int)__ldg(&tb64[s]) : __ldg(&tb32[s]);
                int mv = smkp[s];
                plen += mv;
                if (s >= 1 && mv) {
                    int tp = tags64 ? (int)__ldg(&tb64[s - 1]) : __ldg(&tb32[s - 1]);
                    pnum += __ldg(&trans[tp * CC + t]) + semp[s * CC + t];
                }
            }
#pragma unroll
            for (int off = 16; off >= 1; off >>= 1) {
                pnum += __shfl_xor_sync(FULLM, pnum, off);
                plen += __shfl_xor_sync(FULLM, plen, off);
            }
            int t0 = tags64 ? (int)__ldg(&tb64[0]) : __ldg(&tb32[0]);
            int tl = tags64 ? (int)__ldg(&tb64[plen - 1]) : __ldg(&tb32[plen - 1]);
            if (lane == 0)
                snum[p] = pnum + __ldg(&startt[t0]) + semp[t0] + __ldg(&endt[tl]);
        }
    } else {
        // ---------------- dual-direction, dual-batch recursion ----------------
        bool isf = lane < 16;
        int g = isf ? lane : (lane - 16);
        bool active = (g < CC);
        int gc = active ? g : 0;

        float tk[CC];
#pragma unroll
        for (int k = 0; k < CC; k++) {
            int idx = isf ? (k * CC + gc) : (gc * CC + k);
            float tv = __expf(__ldg(&trans[idx]));
            tk[k] = active ? tv : 0.f;
        }

        float stg = __ldg(&startt[gc]);
        float eng = __ldg(&endt[gc]);
        float vA, vB;
        if (isf) {
            vA = active ? (stg + sem0[gc]) : 0.f;
            vB = active ? (stg + sem1[gc]) : 0.f;
        } else {
            vA = active ? (eng + sem0[(SS - 1) * CC + gc]) : 0.f;
            vB = active ? (eng + sem1[(SS - 1) * CC + gc]) : 0.f;
        }

        int ei  = isf ? (CC + gc) : ((SS - 2) * CC + gc);
        int dei = isf ? CC : -CC;
        int mi  = isf ? 1 : (SS - 1);
        int dmi = isf ? 1 : -1;
        int sbase = isf ? 0 : 16;

        float MA = 0.f, MAl2 = 0.f, MB = 0.f, MBl2 = 0.f;
        float empA = isf ? 0.f : sem0[(SS - 1) * CC + gc];
        float empB = isf ? 0.f : sem1[(SS - 1) * CC + gc];

        auto renorm = [&]() {
            MA = __shfl_sync(FULLM, vA, sbase); MAl2 = MA * L2E;
            MB = __shfl_sync(FULLM, vB, sbase); MBl2 = MB * L2E;
        };
        auto step = [&]() {
            float eA = fast_ex2(fmaf(vA, L2E, -MAl2));
            float eB = fast_ex2(fmaf(vB, L2E, -MBl2));
            float a0 = __shfl_sync(FULLM, eA, sbase + 0);
            float c0 = __shfl_sync(FULLM, eB, sbase + 0);
            float a1 = __shfl_sync(FULLM, eA, sbase + 1);
            float c1 = __shfl_sync(FULLM, eB, sbase + 1);
            float a2 = __shfl_sync(FULLM, eA, sbase + 2);
            float c2 = __shfl_sync(FULLM, eB, sbase + 2);
            float a3 = __shfl_sync(FULLM, eA, sbase + 3);
            float c3 = __shfl_sync(FULLM, eB, sbase + 3);
            float a4 = __shfl_sync(FULLM, eA, sbase + 4);
            float c4 = __shfl_sync(FULLM, eB, sbase + 4);
            float a5 = __shfl_sync(FULLM, eA, sbase + 5);
            float c5 = __shfl_sync(FULLM, eB, sbase + 5);
            float a6 = __shfl_sync(FULLM, eA, sbase + 6);
            float c6 = __shfl_sync(FULLM, eB, sbase + 6);
            float a7 = __shfl_sync(FULLM, eA, sbase + 7);
            float c7 = __shfl_sync(FULLM, eB, sbase + 7);
            float a8 = __shfl_sync(FULLM, eA, sbase + 8);
            float c8 = __shfl_sync(FULLM, eB, sbase + 8);
            float dA0 = fmaf(tk[1], a1, tk[0] * a0); dA0 = fmaf(tk[2], a2, dA0);
            float dB0 = fmaf(tk[1], c1, tk[0] * c0); dB0 = fmaf(tk[2], c2, dB0);
            float dA1 = fmaf(tk[4], a4, tk[3] * a3); dA1 = fmaf(tk[5], a5, dA1);
            float dB1 = fmaf(tk[4], c4, tk[3] * c3); dB1 = fmaf(tk[5], c5, dB1);
            float dA2 = fmaf(tk[7], a7, tk[6] * a6); dA2 = fmaf(tk[8], a8, dA2);
            float dB2 = fmaf(tk[7], c7, tk[6] * c6); dB2 = fmaf(tk[8], c8, dB2);
            float dotA = dA0 + dA1 + dA2;
            float dotB = dB0 + dB1 + dB2;
            float coreA = fmaf(fast_lg2(dotA), LN2, MA);
            float coreB = fmaf(fast_lg2(dotB), LN2, MB);
            float emtA = sem0[ei];
            float emtB = sem1[ei];
            int uA = smk0[mi];
            int uB = smk1[mi];
            float candA = emtA + coreA;
            float candB = emtB + coreB;
            float keepA = isf ? vA : (emtA + vA - empA);
            float keepB = isf ? vB : (emtB + vB - empB);
            vA = uA ? candA : keepA;
            vB = uB ? candB : keepB;
            empA = emtA; empB = emtB;
            ei += dei; mi += dmi;
        };

        // 255 combined iterations = 31 * 8 + 7, renorm every 8
        for (int o = 0; o < 31; o++) {
            renorm();
#pragma unroll
            for (int k = 0; k < 8; k++) step();
        }
        renorm();
#pragma unroll
        for (int k = 0; k < 7; k++) step();

        // tail forward-only step t = S/2 (bwd lanes keep gamma_{S/2})
        {
            renorm();
            float eA = fast_ex2(fmaf(vA, L2E, -MAl2));
            float eB = fast_ex2(fmaf(vB, L2E, -MBl2));
            float a0 = __shfl_sync(FULLM, eA, sbase + 0);
            float c0 = __shfl_sync(FULLM, eB, sbase + 0);
            float a1 = __shfl_sync(FULLM, eA, sbase + 1);
            float c1 = __shfl_sync(FULLM, eB, sbase + 1);
            float a2 = __shfl_sync(FULLM, eA, sbase + 2);
            float c2 = __shfl_sync(FULLM, eB, sbase + 2);
            float a3 = __shfl_sync(FULLM, eA, sbase + 3);
            float c3 = __shfl_sync(FULLM, eB, sbase + 3);
            float a4 = __shfl_sync(FULLM, eA, sbase + 4);
            float c4 = __shfl_sync(FULLM, eB, sbase + 4);
            float a5 = __shfl_sync(FULLM, eA, sbase + 5);
            float c5 = __shfl_sync(FULLM, eB, sbase + 5);
            float a6 = __shfl_sync(FULLM, eA, sbase + 6);
            float c6 = __shfl_sync(FULLM, eB, sbase + 6);
            float a7 = __shfl_sync(FULLM, eA, sbase + 7);
            float c7 = __shfl_sync(FULLM, eB, sbase + 7);
            float a8 = __shfl_sync(FULLM, eA, sbase + 8);
            float c8 = __shfl_sync(FULLM, eB, sbase + 8);
            float dA0 = fmaf(tk[1], a1, tk[0] * a0); dA0 = fmaf(tk[2], a2, dA0);
            float dB0 = fmaf(tk[1], c1, tk[0] * c0); dB0 = fmaf(tk[2], c2, dB0);
            float dA1 = fmaf(tk[4], a4, tk[3] * a3); dA1 = fmaf(tk[5], a5, dA1);
            float dB1 = fmaf(tk[4], c4, tk[3] * c3); dB1 = fmaf(tk[5], c5, dB1);
            float dA2 = fmaf(tk[7], a7, tk[6] * a6); dA2 = fmaf(tk[8], a8, dA2);
            float dB2 = fmaf(tk[7], c7, tk[6] * c6); dB2 = fmaf(tk[8], c8, dB2);
            float dotA = dA0 + dA1 + dA2;
            float dotB = dB0 + dB1 + dB2;
            float coreA = fmaf(fast_lg2(dotA), LN2, MA);
            float coreB = fmaf(fast_lg2(dotB), LN2, MB);
            float candA = sem0[(SS / 2) * CC + gc] + coreA;
            float candB = sem1[(SS / 2) * CC + gc] + coreB;
            if (lane < CC && smk0[SS / 2]) vA = candA;
            if (lane < CC && smk1[SS / 2]) vB = candB;
        }

        // combine: den = LSE_c( alpha[c] + gamma[c] - em[S/2][c] )
        int src = (lane < CC) ? (lane + 16) : lane;
        float vbA = __shfl_sync(FULLM, vA, src);
        float vbB = __shfl_sync(FULLM, vB, src);
        if (lane < CC) {
            shl[0][lane] = vA + vbA - sem0[(SS / 2) * CC + lane];
            shl[1][lane] = vB + vbB - sem1[(SS / 2) * CC + lane];
        }
        __syncwarp();
        if (lane == 0) {
#pragma unroll
            for (int p = 0; p < 2; p++) {
                float m = shl[p][0];
#pragma unroll
                for (int c = 1; c < CC; c++) m = fmaxf(m, shl[p][c]);
                float s = 0.f;
#pragma unroll
                for (int c = 0; c < CC; c++) s += __expf(shl[p][c] - m);
                sden[p] = m + __logf(s);
            }
        }
    }
    __syncthreads();

    if (tid == 0) {
        g_scratch[b0]     = sden[0] - snum[0];
        g_scratch[b0 + 1] = sden[1] - snum[1];
    }
}

// ---------------------------------------------------------------------------
// Kernel 3: deterministic mean over batch
// ---------------------------------------------------------------------------
__global__ __launch_bounds__(32) void k_final(float* __restrict__ out)
{
    int lane = threadIdx.x;
    float s = 0.f;
    for (int i = lane; i < BB; i += 32) s += g_scratch[i];
#pragma unroll
    for (int off = 16; off >= 1; off >>= 1)
        s += __shfl_xor_sync(FULLM, s, off);
    if (lane == 0) out[0] = s / (float)BB;
}

// emissions scratch (B*S*C floats = 2.25 MB)
__device__ float g_em[BB * SS * CC];

extern "C" void kernel_launch(void* const* d_in, const int* in_sizes, int n_in,
                              void* d_out, int out_size)
{
    const float* enc   = (const float*)d_in[0];
    const float* W     = (const float*)d_in[1];
    const float* bias  = (const float*)d_in[2];
    const float* stt   = (const float*)d_in[3];
    const float* ent   = (const float*)d_in[4];
    const float* trans = (const float*)d_in[5];
    const void*  tags  = d_in[6];
    const void*  mask  = d_in[7];
    float* out = (float*)d_out;

    float* em;
    cudaGetSymbolAddress((void**)&em, g_em);

    k_emissions<<<(BB * SS) / 128, 256>>>(enc, W, bias, em);
    k_crf<<<BB / 2, 64>>>(em, stt, ent, trans, tags, mask);
    k_final<<<1, 32>>>(out);
}

// round 15
// speedup vs baseline: 1.2908x; 1.2144x over previous
#include <cuda_runtime.h>
#include <cuda_bf16.h>
#include <math.h>

#define BB 128
#define SS 512
#define EE 768
#define CC 9

#define L2E 1.4426950408889634f
#define LN2 0.6931471805599453f
#define FULLM 0xffffffffu

__device__ float g_scratch[BB];

__device__ __forceinline__ float fast_ex2(float x) {
    float r; asm("ex2.approx.f32 %0, %1;" : "=f"(r) : "f"(x)); return r;
}

// ---------------------------------------------------------------------------
// Kernel 1: emissions = enc @ W^T + b   (exact R5 layout: 53us measured)
// warp = 4 row-groups x 8 k-sublanes; each thread accumulates 4 rows.
// ---------------------------------------------------------------------------
__global__ __launch_bounds__(256) void k_emissions(
    const float* __restrict__ enc, const float* __restrict__ W,
    const float* __restrict__ bias, float* __restrict__ em)
{
    __shared__ float4 sW[CC * 192];
    __shared__ float  sB[CC];

    int tid = threadIdx.x;
    const float4* Wv = reinterpret_cast<const float4*>(W);
    for (int i = tid; i < CC * 192; i += 256) sW[i] = Wv[i];
    if (tid < CC) sB[tid] = bias[tid];
    __syncthreads();

    int warp = tid >> 5, lane = tid & 31;
    int r = lane >> 3, sub = lane & 7;
    int rowbase = blockIdx.x * 128 + warp * 16 + r;

    const float4* e0 = reinterpret_cast<const float4*>(enc) + (size_t)rowbase * 192;

    float acc[4][CC];
#pragma unroll
    for (int j = 0; j < 4; j++)
#pragma unroll
        for (int c = 0; c < CC; c++) acc[j][c] = 0.f;

#pragma unroll 4
    for (int i = 0; i < 24; i++) {
        int k4 = i * 8 + sub;
        float4 ea = __ldg(&e0[k4]);
        float4 eb = __ldg(&e0[768 + k4]);
        float4 ec = __ldg(&e0[1536 + k4]);
        float4 ed = __ldg(&e0[2304 + k4]);
#pragma unroll
        for (int c = 0; c < CC; c++) {
            float4 w = sW[c * 192 + k4];
            acc[0][c] = fmaf(ea.x, w.x, acc[0][c]);
            acc[0][c] = fmaf(ea.y, w.y, acc[0][c]);
            acc[0][c] = fmaf(ea.z, w.z, acc[0][c]);
            acc[0][c] = fmaf(ea.w, w.w, acc[0][c]);
            acc[1][c] = fmaf(eb.x, w.x, acc[1][c]);
            acc[1][c] = fmaf(eb.y, w.y, acc[1][c]);
            acc[1][c] = fmaf(eb.z, w.z, acc[1][c]);
            acc[1][c] = fmaf(eb.w, w.w, acc[1][c]);
            acc[2][c] = fmaf(ec.x, w.x, acc[2][c]);
            acc[2][c] = fmaf(ec.y, w.y, acc[2][c]);
            acc[2][c] = fmaf(ec.z, w.z, acc[2][c]);
            acc[2][c] = fmaf(ec.w, w.w, acc[2][c]);
            acc[3][c] = fmaf(ed.x, w.x, acc[3][c]);
            acc[3][c] = fmaf(ed.y, w.y, acc[3][c]);
            acc[3][c] = fmaf(ed.z, w.z, acc[3][c]);
            acc[3][c] = fmaf(ed.w, w.w, acc[3][c]);
        }
    }

#pragma unroll
    for (int j = 0; j < 4; j++)
#pragma unroll
        for (int c = 0; c < CC; c++) {
            acc[j][c] += __shfl_xor_sync(FULLM, acc[j][c], 4);
            acc[j][c] += __shfl_xor_sync(FULLM, acc[j][c], 2);
            acc[j][c] += __shfl_xor_sync(FULLM, acc[j][c], 1);
        }

#pragma unroll
    for (int j = 0; j < 4; j++) {
        float myv = acc[j][0];
#pragma unroll
        for (int c = 1; c < 8; c++) if (sub == c) myv = acc[j][c];
        size_t obase = (size_t)(rowbase + 4 * j) * CC;
        em[obase + sub] = myv + sB[sub];
        if (sub == 0) em[obase + 8] = acc[j][8] + sB[8];
    }
}

// ---------------------------------------------------------------------------
// Kernel 2: CRF, linear-domain scaled forward/backward. Block=64, 1 batch.
//   Precompute sexp[t][c]=exp(em[t][c]) in smem (both warps, off chain path).
//   warp0 chain: lanes 0-8 fwd p=exp(alpha-KA*ln2); lanes 16-24 bwd
//                r=exp(beta-KB*ln2). No MUFU inside the loop; integer
//                exponent rescale every 8 steps.
//   warp1: numerator (reads em from global/L2).
//   den = ln(sum_c p_c*r_c) + (KA+KB)*ln2  at meeting point t=256.
// ---------------------------------------------------------------------------
__global__ __launch_bounds__(64) void k_crf(
    const float* __restrict__ em_g,
    const float* __restrict__ startt, const float* __restrict__ endt,
    const float* __restrict__ trans,
    const void* __restrict__ tags_raw, const void* __restrict__ mask_raw)
{
    __shared__ float sexp[SS * CC];          // 18KB: exp(emissions)
    __shared__ unsigned char smk[SS];
    __shared__ float snum, sden;
    __shared__ float sh[12];

    int tid = threadIdx.x;
    int lane = tid & 31;
    int w = tid >> 5;
    int b = blockIdx.x;

    // ---------- dtype probes ----------
    const long long* tg64 = (const long long*)tags_raw;
    const int*       tg32 = (const int*)tags_raw;
    long long tprobe = tg64[lane];
    unsigned badt = __ballot_sync(FULLM, (tprobe < 0) || (tprobe >= CC));
    bool tags64 = (badt == 0u);

    const unsigned int* m32 = (const unsigned int*)mask_raw;
    const unsigned char* m8 = (const unsigned char*)mask_raw;
    unsigned int mprobe = m32[lane];
    unsigned badm = __ballot_sync(FULLM, mprobe > 1u);
    bool mask8 = (badm != 0u);

    // ---------- stage exp(emissions) + mask (all 64 threads) ----------
    {
        const float4* src = reinterpret_cast<const float4*>(em_g + (size_t)b * SS * CC);
        float4* dst = reinterpret_cast<float4*>(sexp);
        for (int i = tid; i < (SS * CC) / 4; i += 64) {
            float4 t = __ldg(&src[i]);
            float4 o;
            o.x = fast_ex2(t.x * L2E);
            o.y = fast_ex2(t.y * L2E);
            o.z = fast_ex2(t.z * L2E);
            o.w = fast_ex2(t.w * L2E);
            dst[i] = o;
        }
        if (mask8) {
            const unsigned int* ms = reinterpret_cast<const unsigned int*>(m8 + (size_t)b * SS);
            unsigned int* md = reinterpret_cast<unsigned int*>(smk);
            for (int i = tid; i < SS / 4; i += 64) md[i] = __ldg(&ms[i]);
        } else {
            const unsigned int* ms = m32 + (size_t)b * SS;
            for (int s = tid; s < SS; s += 64)
                smk[s] = (unsigned char)(__ldg(&ms[s]) != 0u);
        }
    }
    __syncthreads();

    if (w == 1) {
        // ---------------- numerator (em from global; L2-resident) -----------
        const long long* tb64 = tg64 + (size_t)b * SS;
        const int*       tb32 = tg32 + (size_t)b * SS;
        const float* emb = em_g + (size_t)b * SS * CC;
        float pnum = 0.f;
        int plen = 0;
#pragma unroll 4
        for (int it = 0; it < SS / 32; it++) {
            int s = it * 32 + lane;
            int t = tags64 ? (int)__ldg(&tb64[s]) : __ldg(&tb32[s]);
            int mv = smk[s];
            plen += mv;
            if (s >= 1 && mv) {
                int tp = tags64 ? (int)__ldg(&tb64[s - 1]) : __ldg(&tb32[s - 1]);
                pnum += __ldg(&trans[tp * CC + t]) + __ldg(&emb[s * CC + t]);
            }
        }
#pragma unroll
        for (int off = 16; off >= 1; off >>= 1) {
            pnum += __shfl_xor_sync(FULLM, pnum, off);
            plen += __shfl_xor_sync(FULLM, plen, off);
        }
        int t0 = tags64 ? (int)__ldg(&tb64[0]) : __ldg(&tb32[0]);
        int tl = tags64 ? (int)__ldg(&tb64[plen - 1]) : __ldg(&tb32[plen - 1]);
        if (lane == 0)
            snum = pnum + __ldg(&startt[t0]) + __ldg(&emb[t0]) + __ldg(&endt[tl]);
    } else {
        // ---------------- linear-domain dual-direction chain ----------------
        bool isf = lane < 16;
        int g = isf ? lane : (lane - 16);
        bool active = (g < CC);
        int gc = active ? g : 0;
        int sbase = isf ? 0 : 16;

        // linear transitions: fwd lane c needs T[k][c]; bwd lane c needs T[c][k]
        float tk[CC];
#pragma unroll
        for (int k = 0; k < CC; k++) {
            int idx = isf ? (k * CC + gc) : (gc * CC + k);
            float tv = __expf(__ldg(&trans[idx]));
            tk[k] = active ? tv : 0.f;
        }

        // init: p(0)=exp(startt+em0); r(511)=exp(endt)
        float v;
        if (isf) v = active ? (__expf(__ldg(&startt[gc])) * sexp[gc]) : 0.f;
        else     v = active ? __expf(__ldg(&endt[gc])) : 0.f;
        int K = 0;

        int ei  = isf ? (CC + gc) : ((SS - 1) * CC + gc);  // fwd: sexp[t]; bwd: sexp[t+1]
        int dei = isf ? CC : -CC;
        int mi  = isf ? 1 : (SS - 1);                      // fwd: mask[t]; bwd: mask[t+1]
        int dmi = isf ? 1 : -1;

        auto rescale = [&]() {
            float pb = __shfl_sync(FULLM, v, sbase);
            unsigned E = (__float_as_uint(pb) >> 23) & 0xFFu;
            float sc = __uint_as_float((254u - E) << 23);   // 2^(127-E)
            v *= sc;
            K += (int)E - 127;
        };
        auto step = [&]() {
            float ld = sexp[ei];
            float z = isf ? v : (v * ld);
            float z0 = __shfl_sync(FULLM, z, sbase + 0);
            float z1 = __shfl_sync(FULLM, z, sbase + 1);
            float z2 = __shfl_sync(FULLM, z, sbase + 2);
            float z3 = __shfl_sync(FULLM, z, sbase + 3);
            float z4 = __shfl_sync(FULLM, z, sbase + 4);
            float z5 = __shfl_sync(FULLM, z, sbase + 5);
            float z6 = __shfl_sync(FULLM, z, sbase + 6);
            float z7 = __shfl_sync(FULLM, z, sbase + 7);
            float z8 = __shfl_sync(FULLM, z, sbase + 8);
            float d0 = fmaf(tk[1], z1, tk[0] * z0); d0 = fmaf(tk[2], z2, d0);
            float d1 = fmaf(tk[4], z4, tk[3] * z3); d1 = fmaf(tk[5], z5, d1);
            float d2 = fmaf(tk[7], z7, tk[6] * z6); d2 = fmaf(tk[8], z8, d2);
            float dot = d0 + d1 + d2;
            float vn = isf ? (dot * ld) : dot;
            int u = smk[mi];
            v = u ? vn : v;
            ei += dei; mi += dmi;
        };

        // 255 combined iterations = 31*8 + 7, rescale every 8
        for (int o = 0; o < 31; o++) {
            rescale();
#pragma unroll
            for (int k = 0; k < 8; k++) step();
        }
        rescale();
#pragma unroll
        for (int k = 0; k < 7; k++) step();

        // tail forward-only step t=256 (bwd lanes keep r)
        {
            rescale();
            float ld = sexp[ei];
            float z = isf ? v : (v * ld);
            float z0 = __shfl_sync(FULLM, z, sbase + 0);
            float z1 = __shfl_sync(FULLM, z, sbase + 1);
            float z2 = __shfl_sync(FULLM, z, sbase + 2);
            float z3 = __shfl_sync(FULLM, z, sbase + 3);
            float z4 = __shfl_sync(FULLM, z, sbase + 4);
            float z5 = __shfl_sync(FULLM, z, sbase + 5);
            float z6 = __shfl_sync(FULLM, z, sbase + 6);
            float z7 = __shfl_sync(FULLM, z, sbase + 7);
            float z8 = __shfl_sync(FULLM, z, sbase + 8);
            float d0 = fmaf(tk[1], z1, tk[0] * z0); d0 = fmaf(tk[2], z2, d0);
            float d1 = fmaf(tk[4], z4, tk[3] * z3); d1 = fmaf(tk[5], z5, d1);
            float d2 = fmaf(tk[7], z7, tk[6] * z6); d2 = fmaf(tk[8], z8, d2);
            float dot = d0 + d1 + d2;
            float vn = dot * ld;
            int u = smk[mi];
            if (isf && u) v = vn;
        }

        // combine: den = ln(sum_c p_c * r_c) + (KA+KB)*ln2
        int src = (lane < 16) ? (lane + 16) : lane;
        float rr = __shfl_sync(FULLM, v, src);
        int KB = __shfl_sync(FULLM, K, 16);
        if (lane < CC) sh[lane] = v * rr;
        __syncwarp();
        if (lane == 0) {
            float s = sh[0];
#pragma unroll
            for (int c = 1; c < CC; c++) s += sh[c];
            sden = logf(s) + (float)(K + KB) * LN2;
        }
    }
    __syncthreads();

    if (tid == 0) g_scratch[b] = sden - snum;
}

// ---------------------------------------------------------------------------
// Kernel 3: deterministic mean over batch
// ---------------------------------------------------------------------------
__global__ __launch_bounds__(32) void k_final(float* __restrict__ out)
{
    int lane = threadIdx.x;
    float s = 0.f;
    for (int i = lane; i < BB; i += 32) s += g_scratch[i];
#pragma unroll
    for (int off = 16; off >= 1; off >>= 1)
        s += __shfl_xor_sync(FULLM, s, off);
    if (lane == 0) out[0] = s / (float)BB;
}

// emissions scratch (B*S*C floats = 2.25 MB)
__device__ float g_em[BB * SS * CC];

extern "C" void kernel_launch(void* const* d_in, const int* in_sizes, int n_in,
                              void* d_out, int out_size)
{
    const float* enc   = (const float*)d_in[0];
    const float* W     = (const float*)d_in[1];
    const float* bias  = (const float*)d_in[2];
    const float* stt   = (const float*)d_in[3];
    const float* ent   = (const float*)d_in[4];
    const float* trans = (const float*)d_in[5];
    const void*  tags  = d_in[6];
    const void*  mask  = d_in[7];
    float* out = (float*)d_out;

    float* em;
    cudaGetSymbolAddress((void**)&em, g_em);

    k_emissions<<<(BB * SS) / 128, 256>>>(enc, W, bias, em);
    k_crf<<<BB, 64>>>(em, stt, ent, trans, tags, mask);
    k_final<<<1, 32>>>(out);
}